// round 4
// baseline (speedup 1.0000x reference)
#include <cuda_runtime.h>

// LSTMModel: B=1024, T=256, I=5, H=64, L=3, O=1, fp32.
// R3: lstm_rec -> warp-local gate transpose (shfl.bfly 4x4), ONE barrier/step,
// double-buffered row-pair-interleaved h in smem. xg_gemm64 -> single full-K
// load phase with 84KB dynamic smem, 2 CTAs/SM.

#define B_SZ 1024
#define T_SZ 256
#define I_SZ 5
#define H_SZ 64
#define G_SZ 256   // 4*H
#define RPB  4     // rows per lstm_rec block
#define GRID_REC (B_SZ / RPB)   // 256

typedef unsigned long long u64;

__device__ float g_xg[(size_t)B_SZ * T_SZ * G_SZ];  // gate preactivations
__device__ float g_h [(size_t)B_SZ * T_SZ * H_SZ];  // layer outputs / h_last
__device__ float g_wT[H_SZ * G_SZ];                 // transposed w_ih (layers 1/2)

__device__ __forceinline__ u64 ffma2(u64 a, u64 b, u64 c) {
    u64 d;
    asm("fma.rn.f32x2 %0, %1, %2, %3;" : "=l"(d) : "l"(a), "l"(b), "l"(c));
    return d;
}
__device__ __forceinline__ u64 pack2(float lo, float hi) {
    u64 d;
    asm("mov.b64 %0, {%1, %2};" : "=l"(d) : "f"(lo), "f"(hi));
    return d;
}
__device__ __forceinline__ float sum2(u64 v) {
    float lo, hi;
    asm("mov.b64 {%0, %1}, %2;" : "=f"(lo), "=f"(hi) : "l"(v));
    return lo + hi;
}

__device__ __forceinline__ float sigf(float x) {
    return __fdividef(1.0f, 1.0f + __expf(-x));
}
__device__ __forceinline__ float tanh_fast(float x) {
    float ax = fabsf(x);
    float e  = __expf(-2.0f * ax);
    float r  = __fdividef(1.0f - e, 1.0f + e);
    return copysignf(r, x);
}

// ---------------------------------------------------------------------------
// Layer 0 input projection: K=5, memory-bound.
// ---------------------------------------------------------------------------
__global__ __launch_bounds__(256) void xg_gemm5(
    const float* __restrict__ x, const float* __restrict__ w,
    const float* __restrict__ b_ih, const float* __restrict__ b_hh)
{
    __shared__ float xs[64 * I_SZ];
    const int t    = threadIdx.x;
    const int row0 = blockIdx.x * 64;

    float wr[I_SZ];
#pragma unroll
    for (int k = 0; k < I_SZ; k++) wr[k] = w[t * I_SZ + k];
    const float bias = b_ih[t] + b_hh[t];

    for (int v = t; v < 64 * I_SZ; v += 256)
        xs[v] = x[(size_t)row0 * I_SZ + v];
    __syncthreads();

#pragma unroll 4
    for (int r = 0; r < 64; r++) {
        float acc = bias;
#pragma unroll
        for (int k = 0; k < I_SZ; k++) acc = fmaf(xs[r * I_SZ + k], wr[k], acc);
        g_xg[(size_t)(row0 + r) * G_SZ + t] = acc;
    }
}

// ---------------------------------------------------------------------------
// Transpose w_ih [256,64] -> g_wT [64,256].
// ---------------------------------------------------------------------------
__global__ __launch_bounds__(256) void transpose_w(const float* __restrict__ w)
{
    int idx = blockIdx.x * 256 + threadIdx.x;
    int g = idx >> 6, k = idx & 63;
    g_wT[k * G_SZ + g] = w[idx];
}

// ---------------------------------------------------------------------------
// Layers 1/2 input projection: [262144,64] @ [64,256] + bias.
// Single full-K load phase (84KB dynamic smem), 64x256 tile, 8x8 register
// tile, FFMA2 packed along the gate dim. 2 CTAs/SM (regs<=128, smem 168KB).
// ---------------------------------------------------------------------------
#define XG_IN_PITCH 68
#define XG_W_PITCH  260
#define XG_SMEM_FLOATS (64 * XG_IN_PITCH + 64 * XG_W_PITCH)
#define XG_SMEM_BYTES  (XG_SMEM_FLOATS * 4)

__global__ __launch_bounds__(256, 2) void xg_gemm64(
    const float* __restrict__ b_ih, const float* __restrict__ b_hh)
{
    extern __shared__ __align__(16) float sm[];
    float (*in_s)[XG_IN_PITCH] = (float(*)[XG_IN_PITCH])sm;
    float (*w_s)[XG_W_PITCH]   = (float(*)[XG_W_PITCH])(sm + 64 * XG_IN_PITCH);

    const int t    = threadIdx.x;
    const int row0 = blockIdx.x * 64;
    const int tcol = t & 31, trow = t >> 5;
    const int g0   = tcol * 8;

    // load input tile [64][64] (coalesced float4)
#pragma unroll
    for (int u = 0; u < 4; u++) {
        int v = u * 256 + t;
        int r = v >> 4, kq = v & 15;
        float4 d = *(const float4*)&g_h[(size_t)(row0 + r) * H_SZ + kq * 4];
        *(float4*)&in_s[r][kq * 4] = d;
    }
    // load weight tile [64][256] from pre-transposed g_wT (coalesced float4)
#pragma unroll
    for (int u = 0; u < 16; u++) {
        int v = u * 256 + t;
        int k = v >> 6, gq = v & 63;
        float4 d = *(const float4*)&g_wT[k * G_SZ + gq * 4];
        *(float4*)&w_s[k][gq * 4] = d;
    }

    u64 acc2[8][4];  // [row][gate-pair]
#pragma unroll
    for (int jp = 0; jp < 4; jp++) {
        float blo = b_ih[g0 + 2 * jp]     + b_hh[g0 + 2 * jp];
        float bhi = b_ih[g0 + 2 * jp + 1] + b_hh[g0 + 2 * jp + 1];
        u64 bp = pack2(blo, bhi);
#pragma unroll
        for (int ii = 0; ii < 8; ii++) acc2[ii][jp] = bp;
    }

    __syncthreads();

#pragma unroll 4
    for (int k = 0; k < 64; k++) {
        u64 adup[8];
#pragma unroll
        for (int ii = 0; ii < 8; ii++) {
            float a = in_s[trow * 8 + ii][k];  // warp broadcast
            adup[ii] = pack2(a, a);
        }
        ulonglong2 bv0 = *(const ulonglong2*)&w_s[k][g0];      // pairs 0,1
        ulonglong2 bv1 = *(const ulonglong2*)&w_s[k][g0 + 4];  // pairs 2,3
        u64 bp[4] = {bv0.x, bv0.y, bv1.x, bv1.y};
#pragma unroll
        for (int ii = 0; ii < 8; ii++)
#pragma unroll
            for (int jp = 0; jp < 4; jp++)
                acc2[ii][jp] = ffma2(adup[ii], bp[jp], acc2[ii][jp]);
    }

#pragma unroll
    for (int ii = 0; ii < 8; ii++) {
        size_t base = (size_t)(row0 + trow * 8 + ii) * G_SZ + g0;
        ulonglong2 o0, o1;
        o0.x = acc2[ii][0]; o0.y = acc2[ii][1];
        o1.x = acc2[ii][2]; o1.y = acc2[ii][3];
        *(ulonglong2*)&g_xg[base]     = o0;
        *(ulonglong2*)&g_xg[base + 4] = o1;
    }
}

// ---------------------------------------------------------------------------
// Recurrent scan, one layer. 256 blocks x 4 batch rows, 256 threads, 2 CTAs/SM.
// Thread t = (cell j = t>>2, gate g = t&3): computes gate column g*64+j for
// all 4 rows (weights register-resident as f32x2 pairs). The cell's 4 gates
// then live in 4 adjacent lanes -> 4x4 in-register transpose via shfl.bfly
// (no smem, no barrier); each thread finishes ONE cell (row=g, hidden=j).
// h lives in double-buffered row-pair-interleaved smem: ONE barrier per step.
//   h_i[buf][q][r][s] = h[row r][k = 2q+s]   (q=0..31, r=0..3, s=0..1)
// ---------------------------------------------------------------------------
__global__ __launch_bounds__(256, 2) void lstm_rec(const float* __restrict__ w_hh,
                                                   int write_all)
{
    __shared__ __align__(16) float h_i[2][256];  // [buf][q*8 + r*2 + s]
    const int t  = threadIdx.x;
    const int b0 = blockIdx.x * RPB;
    const int j  = t >> 2;        // hidden cell index 0..63
    const int g  = t & 3;         // gate index (i,f,g,o)
    const int col = g * 64 + j;   // gate column in [0,256)

    // register-resident weight pairs for gate column `col`
    u64 w2[32];
    {
        const ulonglong2* wv = (const ulonglong2*)(w_hh + col * H_SZ);
#pragma unroll
        for (int q = 0; q < 16; q++) {
            ulonglong2 v = wv[q];
            w2[2 * q]     = v.x;
            w2[2 * q + 1] = v.y;
        }
    }

    // zero both h buffers
    h_i[0][t] = 0.0f;
    h_i[1][t] = 0.0f;

    float c = 0.0f;   // cell state for (row g, hidden j)

    // prefetch xg for step 0
    const size_t xg_base = (size_t)col;
    float xn[RPB];
#pragma unroll
    for (int r = 0; r < RPB; r++)
        xn[r] = g_xg[((size_t)(b0 + r) * T_SZ) * G_SZ + xg_base];

    __syncthreads();

    for (int step = 0; step < T_SZ; step++) {
        const int rb = step & 1;

        u64 acc2[RPB];
#pragma unroll
        for (int r = 0; r < RPB; r++) acc2[r] = pack2(xn[r], 0.0f);

        // prefetch next step's xg under the GEMM
        if (step + 1 < T_SZ) {
#pragma unroll
            for (int r = 0; r < RPB; r++)
                xn[r] = g_xg[((size_t)(b0 + r) * T_SZ + step + 1) * G_SZ + xg_base];
        }

        // GEMM: acc[r] += sum_q h[r][2q..2q+1] . w[2q..2q+1]
        const ulonglong2* hb = (const ulonglong2*)&h_i[rb][0];
#pragma unroll
        for (int q = 0; q < 32; q++) {
            ulonglong2 p01 = hb[2 * q];       // rows 0,1 k-pair q (broadcast)
            ulonglong2 p23 = hb[2 * q + 1];   // rows 2,3
            acc2[0] = ffma2(p01.x, w2[q], acc2[0]);
            acc2[1] = ffma2(p01.y, w2[q], acc2[1]);
            acc2[2] = ffma2(p23.x, w2[q], acc2[2]);
            acc2[3] = ffma2(p23.y, w2[q], acc2[3]);
        }

        float v0 = sum2(acc2[0]);
        float v1 = sum2(acc2[1]);
        float v2 = sum2(acc2[2]);
        float v3 = sum2(acc2[3]);

        // 4x4 in-register transpose across the 4-lane gate group:
        // before: lane g holds M[g][r] (gate g, row r)
        // after:  lane g holds M[q][g] (gate q, row g)
        {
            float s0 = (g & 2) ? v0 : v2;
            float s1 = (g & 2) ? v1 : v3;
            float r0 = __shfl_xor_sync(0xFFFFFFFFu, s0, 2);
            float r1 = __shfl_xor_sync(0xFFFFFFFFu, s1, 2);
            if (g & 2) { v0 = r0; v1 = r1; } else { v2 = r0; v3 = r1; }
            float s2 = (g & 1) ? v0 : v1;
            float s3 = (g & 1) ? v2 : v3;
            float r2 = __shfl_xor_sync(0xFFFFFFFFu, s2, 1);
            float r3 = __shfl_xor_sync(0xFFFFFFFFu, s3, 1);
            if (g & 1) { v0 = r2; v2 = r3; } else { v1 = r2; v3 = r3; }
        }
        // now v0..v3 = i,f,g,o preactivations for (row=g, hidden=j)

        float iv = sigf(v0);
        float fv = sigf(v1);
        float gv = tanh_fast(v2);
        float ov = sigf(v3);
        c = fmaf(fv, c, iv * gv);
        float hv = ov * tanh_fast(c);

        // write h into the other buffer (interleaved layout)
        h_i[rb ^ 1][(j >> 1) * 8 + g * 2 + (j & 1)] = hv;

        if (write_all)
            g_h[((size_t)(b0 + g) * T_SZ + step) * H_SZ + j] = hv;
        else if (step == T_SZ - 1)
            g_h[(size_t)(b0 + g) * H_SZ + j] = hv;

        __syncthreads();  // h complete before next step's GEMM
    }
}

// ---------------------------------------------------------------------------
// Final FC: out[b] = h_last[b,:] . w_fc + b_fc   (O=1)
// ---------------------------------------------------------------------------
__global__ __launch_bounds__(256) void fc_kernel(const float* __restrict__ wfc,
                                                 const float* __restrict__ bfc,
                                                 float* __restrict__ out)
{
    int b = blockIdx.x * 256 + threadIdx.x;
    float acc = bfc[0];
#pragma unroll
    for (int q = 0; q < 16; q++) {
        float4 hv = *(const float4*)&g_h[b * H_SZ + q * 4];
        float4 wv = *(const float4*)&wfc[q * 4];
        acc = fmaf(hv.x, wv.x, acc);
        acc = fmaf(hv.y, wv.y, acc);
        acc = fmaf(hv.z, wv.z, acc);
        acc = fmaf(hv.w, wv.w, acc);
    }
    out[b] = acc;
}

// ---------------------------------------------------------------------------
extern "C" void kernel_launch(void* const* d_in, const int* in_sizes, int n_in,
                              void* d_out, int out_size)
{
    (void)in_sizes; (void)n_in; (void)out_size;
    const float* x     = (const float*)d_in[0];
    const float* w_ih0 = (const float*)d_in[1];
    const float* w_hh0 = (const float*)d_in[2];
    const float* b_ih0 = (const float*)d_in[3];
    const float* b_hh0 = (const float*)d_in[4];
    const float* w_ih1 = (const float*)d_in[5];
    const float* w_hh1 = (const float*)d_in[6];
    const float* b_ih1 = (const float*)d_in[7];
    const float* b_hh1 = (const float*)d_in[8];
    const float* w_ih2 = (const float*)d_in[9];
    const float* w_hh2 = (const float*)d_in[10];
    const float* b_ih2 = (const float*)d_in[11];
    const float* b_hh2 = (const float*)d_in[12];
    const float* w_fc  = (const float*)d_in[13];
    const float* b_fc  = (const float*)d_in[14];
    float* out = (float*)d_out;

    const int NROWS = B_SZ * T_SZ;  // 262144

    // allow >48KB dynamic smem for xg_gemm64 (host-side attr, graph-safe)
    cudaFuncSetAttribute(xg_gemm64, cudaFuncAttributeMaxDynamicSharedMemorySize,
                         XG_SMEM_BYTES);

    // layer 0
    xg_gemm5<<<NROWS / 64, 256>>>(x, w_ih0, b_ih0, b_hh0);
    lstm_rec<<<GRID_REC, 256>>>(w_hh0, 1);

    // layer 1
    transpose_w<<<64, 256>>>(w_ih1);
    xg_gemm64<<<NROWS / 64, 256, XG_SMEM_BYTES>>>(b_ih1, b_hh1);
    lstm_rec<<<GRID_REC, 256>>>(w_hh1, 1);

    // layer 2 (only last timestep's h is needed downstream)
    transpose_w<<<64, 256>>>(w_ih2);
    xg_gemm64<<<NROWS / 64, 256, XG_SMEM_BYTES>>>(b_ih2, b_hh2);
    lstm_rec<<<GRID_REC, 256>>>(w_hh2, 0);

    // final projection
    fc_kernel<<<B_SZ / 256, 256>>>(w_fc, b_fc, out);
}

// round 5
// speedup vs baseline: 1.1203x; 1.1203x over previous
#include <cuda_runtime.h>

// LSTMModel: B=1024, T=256, I=5, H=64, L=3, O=1, fp32.
// R4: rec reverted to R2 structure (smem gates, coalesced xg prefetch) with a
// BALANCED 304-CTA grid (112x4 + 192x3 rows -> <=7 rows/SM); layer-0 xg fused
// into rec (xg_gemm5 removed); xg_gemm64 inner loop reads pre-duplicated
// (v,v) u64 pairs from smem (no per-k scalar LDS / pack MOVs).

#define B_SZ 1024
#define T_SZ 256
#define I_SZ 5
#define H_SZ 64
#define G_SZ 256   // 4*H
#define N4   112           // CTAs carrying 4 rows; rest carry 3
#define GRID_REC 304       // 112*4 + 192*3 = 1024

typedef unsigned long long u64;

__device__ float g_xg[(size_t)B_SZ * T_SZ * G_SZ];  // gate preactivations (layers 1,2)
__device__ float g_h [(size_t)B_SZ * T_SZ * H_SZ];  // layer outputs / h_last
__device__ float g_wT[H_SZ * G_SZ];                 // transposed w_ih (layers 1/2)

__device__ __forceinline__ u64 ffma2(u64 a, u64 b, u64 c) {
    u64 d;
    asm("fma.rn.f32x2 %0, %1, %2, %3;" : "=l"(d) : "l"(a), "l"(b), "l"(c));
    return d;
}
__device__ __forceinline__ u64 pack2(float lo, float hi) {
    u64 d;
    asm("mov.b64 %0, {%1, %2};" : "=l"(d) : "f"(lo), "f"(hi));
    return d;
}
__device__ __forceinline__ float sum2(u64 v) {
    float lo, hi;
    asm("mov.b64 {%0, %1}, %2;" : "=f"(lo), "=f"(hi) : "l"(v));
    return lo + hi;
}

__device__ __forceinline__ float sigf(float x) {
    return __fdividef(1.0f, 1.0f + __expf(-x));
}
__device__ __forceinline__ float tanh_fast(float x) {
    float ax = fabsf(x);
    float e  = __expf(-2.0f * ax);
    float r  = __fdividef(1.0f - e, 1.0f + e);
    return copysignf(r, x);
}

// ---------------------------------------------------------------------------
// Transpose w_ih [256,64] -> g_wT [64,256].
// ---------------------------------------------------------------------------
__global__ __launch_bounds__(256) void transpose_w(const float* __restrict__ w)
{
    int idx = blockIdx.x * 256 + threadIdx.x;
    int g = idx >> 6, k = idx & 63;
    g_wT[k * G_SZ + g] = w[idx];
}

// ---------------------------------------------------------------------------
// Layers 1/2 input projection: [262144,64] @ [64,256] + bias -> g_xg.
// Input tile stored in smem as duplicated u64 pairs (v,v): inner loop does
// one LDS.64 broadcast per (row,k) feeding FFMA2 directly. 97KB dyn smem,
// 2 CTAs/SM, single sync.
// ---------------------------------------------------------------------------
#define XG_W_PITCH 260
#define XG_SMEM_BYTES (64 * 64 * 8 + 64 * XG_W_PITCH * 4)

__global__ __launch_bounds__(256, 2) void xg_gemm64(
    const float* __restrict__ b_ih, const float* __restrict__ b_hh)
{
    extern __shared__ __align__(16) unsigned char smraw[];
    u64   (*a2_s)[64]         = (u64(*)[64])smraw;                       // 32 KB
    float (*w_s)[XG_W_PITCH]  = (float(*)[XG_W_PITCH])(smraw + 64 * 64 * 8);

    const int t    = threadIdx.x;
    const int row0 = blockIdx.x * 64;
    const int tcol = t & 31, trow = t >> 5;
    const int g0   = tcol * 8;

    // input tile [64 rows][64 k] as duplicated pairs
#pragma unroll
    for (int u = 0; u < 4; u++) {
        int v = u * 256 + t;
        int r = v >> 4, kq = v & 15;
        float4 d = *(const float4*)&g_h[(size_t)(row0 + r) * H_SZ + kq * 4];
        ulonglong2 e0, e1;
        e0.x = pack2(d.x, d.x); e0.y = pack2(d.y, d.y);
        e1.x = pack2(d.z, d.z); e1.y = pack2(d.w, d.w);
        *(ulonglong2*)&a2_s[r][kq * 4]     = e0;
        *(ulonglong2*)&a2_s[r][kq * 4 + 2] = e1;
    }
    // weight tile [64][256] from pre-transposed g_wT
#pragma unroll
    for (int u = 0; u < 16; u++) {
        int v = u * 256 + t;
        int k = v >> 6, gq = v & 63;
        float4 d = *(const float4*)&g_wT[k * G_SZ + gq * 4];
        *(float4*)&w_s[k][gq * 4] = d;
    }

    u64 acc2[8][4];  // [row][gate-pair]
#pragma unroll
    for (int jp = 0; jp < 4; jp++) {
        float blo = b_ih[g0 + 2 * jp]     + b_hh[g0 + 2 * jp];
        float bhi = b_ih[g0 + 2 * jp + 1] + b_hh[g0 + 2 * jp + 1];
        u64 bp = pack2(blo, bhi);
#pragma unroll
        for (int ii = 0; ii < 8; ii++) acc2[ii][jp] = bp;
    }

    __syncthreads();

#pragma unroll 4
    for (int k = 0; k < 64; k++) {
        u64 adup[8];
#pragma unroll
        for (int ii = 0; ii < 8; ii++)
            adup[ii] = a2_s[trow * 8 + ii][k];   // LDS.64 broadcast
        ulonglong2 bv0 = *(const ulonglong2*)&w_s[k][g0];
        ulonglong2 bv1 = *(const ulonglong2*)&w_s[k][g0 + 4];
        u64 bp[4] = {bv0.x, bv0.y, bv1.x, bv1.y};
#pragma unroll
        for (int ii = 0; ii < 8; ii++)
#pragma unroll
            for (int jp = 0; jp < 4; jp++)
                acc2[ii][jp] = ffma2(adup[ii], bp[jp], acc2[ii][jp]);
    }

#pragma unroll
    for (int ii = 0; ii < 8; ii++) {
        size_t base = (size_t)(row0 + trow * 8 + ii) * G_SZ + g0;
        ulonglong2 o0, o1;
        o0.x = acc2[ii][0]; o0.y = acc2[ii][1];
        o1.x = acc2[ii][2]; o1.y = acc2[ii][3];
        *(ulonglong2*)&g_xg[base]     = o0;
        *(ulonglong2*)&g_xg[base + 4] = o1;
    }
}

// ---------------------------------------------------------------------------
// Recurrent scan, one layer. Balanced grid: 304 CTAs (first 112 own 4 rows,
// rest own 3), 256 threads, 2 CTAs/SM -> <=7 rows/SM. R2 structure: thread t
// computes gate column t for its rows (w_hh row t register-resident as f32x2
// pairs, h broadcast from smem); gates exchanged via smem; 1 cell/thread
// epilogue. mode 0: layer 0 -> xg fused (K=5 weights in regs, x staged in
// double-buffered smem), write full h seq. mode 1: read g_xg, write full h
// seq. mode 2: read g_xg, write only t=T-1 compact.
// ---------------------------------------------------------------------------
__global__ __launch_bounds__(256, 2) void lstm_rec(
    const float* __restrict__ w_hh,
    const float* __restrict__ x,      // mode 0 only
    const float* __restrict__ w_ih,   // mode 0 only [256,5]
    const float* __restrict__ b_ih,   // mode 0 only
    const float* __restrict__ b_hh,   // mode 0 only
    int mode)
{
    __shared__ __align__(16) float h_s[4][H_SZ];     // 1 KB
    __shared__ float gates_s[4][G_SZ];               // 4 KB
    __shared__ float xs[2][4][8];                    // mode-0 x staging
    const int t   = threadIdx.x;                     // gate column
    const int bid = blockIdx.x;
    const bool r4 = (bid < N4);
    const int b0  = r4 ? bid * 4 : N4 * 4 + (bid - N4) * 3;
    const int rows = r4 ? 4 : 3;

    // register-resident recurrent weight pairs (w_hh row t)
    u64 w2[32];
    {
        const ulonglong2* wv = (const ulonglong2*)(w_hh + t * H_SZ);
#pragma unroll
        for (int q = 0; q < 16; q++) {
            ulonglong2 v = wv[q];
            w2[2 * q]     = v.x;
            w2[2 * q + 1] = v.y;
        }
    }

    // mode-0: input weights + bias + step-0 x staging
    float wx[I_SZ];
    float bias = 0.0f;
    if (mode == 0) {
#pragma unroll
        for (int k = 0; k < I_SZ; k++) wx[k] = w_ih[t * I_SZ + k];
        bias = b_ih[t] + b_hh[t];
        if (t < 4 * I_SZ) {
            int r = t / I_SZ, k = t % I_SZ;
            if (r < rows)
                xs[0][r][k] = x[((size_t)(b0 + r) * T_SZ) * I_SZ + k];
        }
    }

    ((float*)h_s)[t] = 0.0f;   // 256 floats exactly

    const int re = t >> 6, je = t & 63;
    const bool cell = (t < rows * 64);
    float c = 0.0f;

    // mode 1/2: prefetch xg for step 0 (coalesced: 32 consecutive cols/warp)
    float xn[4];
    if (mode != 0) {
#pragma unroll
        for (int r = 0; r < 3; r++)
            xn[r] = g_xg[((size_t)(b0 + r) * T_SZ) * G_SZ + t];
        if (r4) xn[3] = g_xg[((size_t)(b0 + 3) * T_SZ) * G_SZ + t];
    }

    __syncthreads();

    for (int step = 0; step < T_SZ; step++) {
        u64 acc2[4];
        if (mode == 0) {
            const int cur = step & 1;
            float a0 = bias, a1 = bias, a2v = bias, a3 = bias;
#pragma unroll
            for (int k = 0; k < I_SZ; k++) {
                a0  = fmaf(xs[cur][0][k], wx[k], a0);
                a1  = fmaf(xs[cur][1][k], wx[k], a1);
                a2v = fmaf(xs[cur][2][k], wx[k], a2v);
                a3  = fmaf(xs[cur][3][k], wx[k], a3);
            }
            acc2[0] = pack2(a0, 0.0f);  acc2[1] = pack2(a1, 0.0f);
            acc2[2] = pack2(a2v, 0.0f); acc2[3] = pack2(a3, 0.0f);
            // prefetch next step's x into the other buffer
            if (step + 1 < T_SZ && t < 4 * I_SZ) {
                int r = t / I_SZ, k = t % I_SZ;
                if (r < rows)
                    xs[cur ^ 1][r][k] = x[((size_t)(b0 + r) * T_SZ + step + 1) * I_SZ + k];
            }
        } else {
#pragma unroll
            for (int r = 0; r < 4; r++) acc2[r] = pack2(xn[r], 0.0f);
            if (step + 1 < T_SZ) {
#pragma unroll
                for (int r = 0; r < 3; r++)
                    xn[r] = g_xg[((size_t)(b0 + r) * T_SZ + step + 1) * G_SZ + t];
                if (r4)
                    xn[3] = g_xg[((size_t)(b0 + 3) * T_SZ + step + 1) * G_SZ + t];
            }
        }

        // GEMM: gates[r][t] += sum_k h[r][k] * w_hh[t][k]  (rows 0-2 always)
        const ulonglong2* h2 = (const ulonglong2*)&h_s[0][0];
#pragma unroll
        for (int q = 0; q < 16; q++) {
            const u64 wa = w2[2 * q], wb = w2[2 * q + 1];
            ulonglong2 p0 = h2[0 * 16 + q];
            acc2[0] = ffma2(p0.x, wa, acc2[0]);
            acc2[0] = ffma2(p0.y, wb, acc2[0]);
            ulonglong2 p1 = h2[1 * 16 + q];
            acc2[1] = ffma2(p1.x, wa, acc2[1]);
            acc2[1] = ffma2(p1.y, wb, acc2[1]);
            ulonglong2 p2 = h2[2 * 16 + q];
            acc2[2] = ffma2(p2.x, wa, acc2[2]);
            acc2[2] = ffma2(p2.y, wb, acc2[2]);
        }
        if (r4) {       // row 3 only for 4-row CTAs (block-uniform branch)
#pragma unroll
            for (int q = 0; q < 16; q++) {
                ulonglong2 p3 = h2[3 * 16 + q];
                acc2[3] = ffma2(p3.x, w2[2 * q],     acc2[3]);
                acc2[3] = ffma2(p3.y, w2[2 * q + 1], acc2[3]);
            }
        }
        gates_s[0][t] = sum2(acc2[0]);
        gates_s[1][t] = sum2(acc2[1]);
        gates_s[2][t] = sum2(acc2[2]);
        if (r4) gates_s[3][t] = sum2(acc2[3]);
        __syncthreads();

        // elementwise LSTM cell: one cell per thread
        if (cell) {
            float iv = sigf(gates_s[re][je]);
            float fv = sigf(gates_s[re][64 + je]);
            float gv = tanh_fast(gates_s[re][128 + je]);
            float ov = sigf(gates_s[re][192 + je]);
            c = fmaf(fv, c, iv * gv);
            float hv = ov * tanh_fast(c);
            h_s[re][je] = hv;
            if (mode != 2)
                g_h[((size_t)(b0 + re) * T_SZ + step) * H_SZ + je] = hv;
            else if (step == T_SZ - 1)
                g_h[(size_t)(b0 + re) * H_SZ + je] = hv;
        }
        __syncthreads();
    }
}

// ---------------------------------------------------------------------------
// Final FC: out[b] = h_last[b,:] . w_fc + b_fc   (O=1)
// ---------------------------------------------------------------------------
__global__ __launch_bounds__(256) void fc_kernel(const float* __restrict__ wfc,
                                                 const float* __restrict__ bfc,
                                                 float* __restrict__ out)
{
    int b = blockIdx.x * 256 + threadIdx.x;
    float acc = bfc[0];
#pragma unroll
    for (int q = 0; q < 16; q++) {
        float4 hv = *(const float4*)&g_h[b * H_SZ + q * 4];
        float4 wv = *(const float4*)&wfc[q * 4];
        acc = fmaf(hv.x, wv.x, acc);
        acc = fmaf(hv.y, wv.y, acc);
        acc = fmaf(hv.z, wv.z, acc);
        acc = fmaf(hv.w, wv.w, acc);
    }
    out[b] = acc;
}

// ---------------------------------------------------------------------------
extern "C" void kernel_launch(void* const* d_in, const int* in_sizes, int n_in,
                              void* d_out, int out_size)
{
    (void)in_sizes; (void)n_in; (void)out_size;
    const float* x     = (const float*)d_in[0];
    const float* w_ih0 = (const float*)d_in[1];
    const float* w_hh0 = (const float*)d_in[2];
    const float* b_ih0 = (const float*)d_in[3];
    const float* b_hh0 = (const float*)d_in[4];
    const float* w_ih1 = (const float*)d_in[5];
    const float* w_hh1 = (const float*)d_in[6];
    const float* b_ih1 = (const float*)d_in[7];
    const float* b_hh1 = (const float*)d_in[8];
    const float* w_ih2 = (const float*)d_in[9];
    const float* w_hh2 = (const float*)d_in[10];
    const float* b_ih2 = (const float*)d_in[11];
    const float* b_hh2 = (const float*)d_in[12];
    const float* w_fc  = (const float*)d_in[13];
    const float* b_fc  = (const float*)d_in[14];
    float* out = (float*)d_out;

    const int NROWS = B_SZ * T_SZ;  // 262144

    cudaFuncSetAttribute(xg_gemm64, cudaFuncAttributeMaxDynamicSharedMemorySize,
                         XG_SMEM_BYTES);

    // layer 0 (xg fused into rec)
    lstm_rec<<<GRID_REC, 256>>>(w_hh0, x, w_ih0, b_ih0, b_hh0, 0);

    // layer 1
    transpose_w<<<64, 256>>>(w_ih1);
    xg_gemm64<<<NROWS / 64, 256, XG_SMEM_BYTES>>>(b_ih1, b_hh1);
    lstm_rec<<<GRID_REC, 256>>>(w_hh1, nullptr, nullptr, nullptr, nullptr, 1);

    // layer 2 (only last timestep's h needed downstream)
    transpose_w<<<64, 256>>>(w_ih2);
    xg_gemm64<<<NROWS / 64, 256, XG_SMEM_BYTES>>>(b_ih2, b_hh2);
    lstm_rec<<<GRID_REC, 256>>>(w_hh2, nullptr, nullptr, nullptr, nullptr, 2);

    // final projection
    fc_kernel<<<B_SZ / 256, 256>>>(w_fc, b_fc, out);
}